// round 1
// baseline (speedup 1.0000x reference)
#include <cuda_runtime.h>

#define MAXN 50000
#define MAXE 1250000
#define DD   64

// ---------------- scratch (static device globals; allocation-free) ----------------
__device__ int   g_is64;
__device__ float g_deg[MAXN];
__device__ float g_dis[MAXN];
__device__ int   g_cnt[MAXN];
__device__ int   g_ptr[MAXN];
__device__ int   g_bsum[64];
__device__ int   g_boff[64];
__device__ __align__(16) int2  g_csr[MAXE];       // .x = src row, .y = bits(norm)
__device__ __align__(16) float g_h [MAXN * DD];
__device__ __align__(16) float g_xa[MAXN * DD];
__device__ __align__(16) float g_xb[MAXN * DD];

// ---------------- int64 vs int32 edge_index detection ----------------
// If edge_index is int64 (values < 2^31, nonneg), every odd int32 word is 0.
__global__ void detect_kernel(const int* __restrict__ ei) {
    bool is64 = true;
    for (int i = 0; i < 64; ++i)
        if (ei[2 * i + 1] != 0) { is64 = false; break; }
    g_is64 = is64 ? 1 : 0;
}

__device__ __forceinline__ void load_edge(const int* __restrict__ ei, int e, int E,
                                          int is64, int& r, int& c) {
    if (is64) { r = ei[2 * e]; c = ei[2 * (E + e)]; }
    else      { r = ei[e];     c = ei[E + e]; }
}

// ---------------- graph normalization + CSR build ----------------
__global__ void init_kernel(int n) {
    int i = blockIdx.x * blockDim.x + threadIdx.x;
    if (i < n) { g_deg[i] = 2.0f; g_cnt[i] = 0; }   // improved=True self-loop weight
}

__global__ void deg_kernel(const int* __restrict__ ei, const float* __restrict__ w, int E) {
    int e = blockIdx.x * blockDim.x + threadIdx.x;
    if (e >= E) return;
    int is64 = g_is64;
    int r, c; load_edge(ei, e, E, is64, r, c);
    (void)r;
    atomicAdd(&g_deg[c], w[e]);
    atomicAdd(&g_cnt[c], 1);
}

__global__ void dis_kernel(int n) {
    int i = blockIdx.x * blockDim.x + threadIdx.x;
    if (i < n) {
        float d = g_deg[i];
        g_dis[i] = (d > 0.0f) ? rsqrtf(d) : 0.0f;
    }
}

__global__ void scan1_kernel(int n) {
    __shared__ int s[1024];
    int t = threadIdx.x;
    int i = blockIdx.x * 1024 + t;
    int v = (i < n) ? g_cnt[i] : 0;
    s[t] = v;
    __syncthreads();
    for (int off = 1; off < 1024; off <<= 1) {
        int x = (t >= off) ? s[t - off] : 0;
        __syncthreads();
        s[t] += x;
        __syncthreads();
    }
    if (i < n) g_ptr[i] = s[t] - v;              // block-local exclusive
    if (t == 1023) g_bsum[blockIdx.x] = s[1023];
}

__global__ void scan2_kernel(int nb) {
    int run = 0;
    for (int b = 0; b < nb; ++b) { g_boff[b] = run; run += g_bsum[b]; }
}

__global__ void scan3_kernel(int n) {
    int i = blockIdx.x * blockDim.x + threadIdx.x;
    if (i < n) { g_ptr[i] += g_boff[i >> 10]; g_cnt[i] = 0; }
}

__global__ void fill_kernel(const int* __restrict__ ei, const float* __restrict__ w, int E) {
    int e = blockIdx.x * blockDim.x + threadIdx.x;
    if (e >= E) return;
    int is64 = g_is64;
    int r, c; load_edge(ei, e, E, is64, r, c);
    float nm = g_dis[r] * w[e] * g_dis[c];
    int pos = g_ptr[c] + atomicAdd(&g_cnt[c], 1);
    g_csr[pos] = make_int2(r, __float_as_int(nm));
}

// ---------------- per-layer: H = X @ W (64x64), W in smem, 2 nodes x 4 feats / thread ----------------
__global__ void gemm_kernel(const float* __restrict__ X, const float* __restrict__ W,
                            float* __restrict__ H, int n) {
    __shared__ float4 sW[64 * 16];     // W[k][j] as float4 groups over j
    __shared__ float  sx[32 * 64];     // 32 node rows
    int tid = threadIdx.x;
    const float4* W4 = (const float4*)W;
#pragma unroll
    for (int i = 0; i < 4; ++i) sW[tid + i * 256] = W4[tid + i * 256];
    int base = blockIdx.x * 32;
#pragma unroll
    for (int i = 0; i < 8; ++i) {
        int idx = tid + i * 256;
        int r = idx >> 6, k = idx & 63;
        int gn = base + r;
        sx[idx] = (gn < n) ? X[gn * 64 + k] : 0.0f;
    }
    __syncthreads();

    int pair = tid >> 4;          // 0..15 -> 2 nodes each
    int t    = tid & 15;          // feature group (4 feats)
    int ln0  = pair * 2;
    float4 a0 = make_float4(0, 0, 0, 0), a1 = make_float4(0, 0, 0, 0);
#pragma unroll
    for (int k = 0; k < 64; ++k) {
        float4 w4 = sW[k * 16 + t];
        float xa = sx[ln0 * 64 + k];
        float xb = sx[(ln0 + 1) * 64 + k];
        a0.x = fmaf(w4.x, xa, a0.x); a0.y = fmaf(w4.y, xa, a0.y);
        a0.z = fmaf(w4.z, xa, a0.z); a0.w = fmaf(w4.w, xa, a0.w);
        a1.x = fmaf(w4.x, xb, a1.x); a1.y = fmaf(w4.y, xb, a1.y);
        a1.z = fmaf(w4.z, xb, a1.z); a1.w = fmaf(w4.w, xb, a1.w);
    }
    float4* H4 = (float4*)H;
    int n0 = base + ln0;
    if (n0 < n)     H4[n0 * 16 + t]       = a0;
    if (n0 + 1 < n) H4[(n0 + 1) * 16 + t] = a1;
}

// ---------------- aggregation: warp per node, float2 lanes, CSR pull + self + bias + relu ----------------
__global__ void agg_kernel(const float* __restrict__ H, float* __restrict__ Xo,
                           const float* __restrict__ bias, int n) {
    int gid  = blockIdx.x * blockDim.x + threadIdx.x;
    int node = gid >> 5;
    int lane = gid & 31;
    if (node >= n) return;
    const float2* hp = (const float2*)H;

    float dsn = g_dis[node];
    float sn  = 2.0f * dsn * dsn;                // self-loop: dis*2.0*dis
    float2 hv = hp[node * 32 + lane];
    float2 a0 = make_float2(hv.x * sn, hv.y * sn);
    float2 a1 = make_float2(0.0f, 0.0f);

    int s   = g_ptr[node];
    int end = s + g_cnt[node];
    int e   = s;
    for (; e + 1 < end; e += 2) {
        int2 e0 = g_csr[e];
        int2 e1 = g_csr[e + 1];
        float2 h0 = hp[e0.x * 32 + lane];
        float2 h1 = hp[e1.x * 32 + lane];
        float n0 = __int_as_float(e0.y);
        float n1 = __int_as_float(e1.y);
        a0.x = fmaf(h0.x, n0, a0.x); a0.y = fmaf(h0.y, n0, a0.y);
        a1.x = fmaf(h1.x, n1, a1.x); a1.y = fmaf(h1.y, n1, a1.y);
    }
    if (e < end) {
        int2 e0 = g_csr[e];
        float2 h0 = hp[e0.x * 32 + lane];
        float n0 = __int_as_float(e0.y);
        a0.x = fmaf(h0.x, n0, a0.x); a0.y = fmaf(h0.y, n0, a0.y);
    }
    float2 b2 = ((const float2*)bias)[lane];
    float2 r;
    r.x = fmaxf(a0.x + a1.x + b2.x, 0.0f);
    r.y = fmaxf(a0.y + a1.y + b2.y, 0.0f);
    ((float2*)Xo)[node * 32 + lane] = r;
}

// ---------------- final projection: out[n] = x[n] . Wf + bf ----------------
__global__ void final_kernel(const float* __restrict__ X, const float* __restrict__ Wf,
                             const float* __restrict__ bf, float* __restrict__ out, int n) {
    int gid  = blockIdx.x * blockDim.x + threadIdx.x;
    int node = gid >> 5;
    int lane = gid & 31;
    if (node >= n) return;
    float2 xv = ((const float2*)X)[node * 32 + lane];
    float2 wv = ((const float2*)Wf)[lane];
    float s = xv.x * wv.x + xv.y * wv.y;
#pragma unroll
    for (int off = 16; off > 0; off >>= 1)
        s += __shfl_down_sync(0xffffffffu, s, off);
    if (lane == 0) out[node] = s + bf[0];
}

// ---------------- launch ----------------
extern "C" void kernel_launch(void* const* d_in, const int* in_sizes, int n_in,
                              void* d_out, int out_size) {
    const float* x  = (const float*)d_in[0];
    const int*   ei = (const int*)d_in[1];
    const float* w  = (const float*)d_in[2];
    const float* Ws = (const float*)d_in[3];
    const float* bs = (const float*)d_in[4];
    const float* Wf = (const float*)d_in[5];
    const float* bf = (const float*)d_in[6];

    int n = in_sizes[0] / DD;
    int E = in_sizes[2];
    int L = in_sizes[3] / (DD * DD);

    float *xa, *xb, *h;
    cudaGetSymbolAddress((void**)&xa, g_xa);
    cudaGetSymbolAddress((void**)&xb, g_xb);
    cudaGetSymbolAddress((void**)&h,  g_h);

    int nb256 = (n + 255) / 256;
    int eb256 = (E + 255) / 256;
    int nscan = (n + 1023) / 1024;

    detect_kernel<<<1, 1>>>(ei);
    init_kernel<<<nb256, 256>>>(n);
    deg_kernel<<<eb256, 256>>>(ei, w, E);
    dis_kernel<<<nb256, 256>>>(n);
    scan1_kernel<<<nscan, 1024>>>(n);
    scan2_kernel<<<1, 1>>>(nscan);
    scan3_kernel<<<nb256, 256>>>(n);
    fill_kernel<<<eb256, 256>>>(ei, w, E);

    const float* xin = x;
    float* bufs[2] = {xa, xb};
    for (int l = 0; l < L; ++l) {
        gemm_kernel<<<(n + 31) / 32, 256>>>(xin, Ws + (size_t)l * DD * DD, h, n);
        agg_kernel<<<(n * 32 + 255) / 256, 256>>>(h, bufs[l & 1], bs + (size_t)l * DD, n);
        xin = bufs[l & 1];
    }
    final_kernel<<<(n * 32 + 255) / 256, 256>>>(xin, Wf, bf, (float*)d_out, n);
}